// round 3
// baseline (speedup 1.0000x reference)
#include <cuda_runtime.h>
#include <math.h>

#define B_  64
#define T_  512
#define I_  1024
#define H_  1024
#define M_  (B_*T_)

// ---------------------------------------------------------------------------
// Scratch (device globals — no allocation allowed)
// ---------------------------------------------------------------------------
__device__ float g_h[2][B_*H_];            // h3 double buffer (2 x 256 KB)
__device__ unsigned g_cnt;                 // barrier arrival counter (returns to 0)
__device__ volatile unsigned g_gen;        // barrier generation (monotonic, wrap-safe)

#define SCAN_BLOCKS 128

__device__ __forceinline__ void grid_barrier() {
    __syncthreads();
    if (threadIdx.x == 0) {
        __threadfence();                               // release my block's stores
        unsigned gen = g_gen;                          // snapshot before arriving
        if (atomicAdd(&g_cnt, 1u) == SCAN_BLOCKS - 1) {
            atomicExch(&g_cnt, 0u);
            __threadfence();
            g_gen = gen + 1;                           // release everyone
        } else {
            while (g_gen == gen) { }                   // spin (volatile load)
        }
        __threadfence();
    }
    __syncthreads();
}

// ---------------------------------------------------------------------------
// Kernel A: xw = x @ W^T + bW   -> written into out1 region of d_out
// C[M,H] ; M=32768, K=I=1024. Both operands K-contiguous (NT GEMM).
// Tile 128x64x16, 256 threads, 8x4 micro-tile.
// ---------------------------------------------------------------------------
#define BM 128
#define BN 64
#define BK 16
#define AST 132   // BM + 4 pad (keeps float4 alignment: 132*4 % 16 == 0)
#define BST 68    // BN + 4 pad

__global__ __launch_bounds__(256, 3)
void xw_gemm_kernel(const float* __restrict__ X, const float* __restrict__ W,
                    const float* __restrict__ bW, float* __restrict__ C) {
    __shared__ float As[BK * AST];
    __shared__ float Bs[BK * BST];

    const int tid = threadIdx.x;
    const int tx  = tid & 15;        // 0..15 -> 4 cols each
    const int ty  = tid >> 4;        // 0..15 -> 8 rows each
    const int m0  = blockIdx.y * BM;
    const int n0  = blockIdx.x * BN;

    float acc[8][4];
#pragma unroll
    for (int i = 0; i < 8; ++i)
#pragma unroll
        for (int j = 0; j < 4; ++j) acc[i][j] = 0.f;

    for (int k0 = 0; k0 < I_; k0 += BK) {
        // stage A tile: 128x16 floats = 512 float4, 2 per thread; store transposed
#pragma unroll
        for (int s = 0; s < 2; ++s) {
            int idx = tid + s * 256;
            int r   = idx >> 2;
            int c4  = (idx & 3) * 4;
            float4 v = *(const float4*)&X[(size_t)(m0 + r) * I_ + k0 + c4];
            As[(c4 + 0) * AST + r] = v.x;
            As[(c4 + 1) * AST + r] = v.y;
            As[(c4 + 2) * AST + r] = v.z;
            As[(c4 + 3) * AST + r] = v.w;
        }
        // stage B tile: 64x16 floats = 256 float4, 1 per thread; store transposed
        {
            int r  = tid >> 2;
            int c4 = (tid & 3) * 4;
            float4 v = *(const float4*)&W[(size_t)(n0 + r) * I_ + k0 + c4];
            Bs[(c4 + 0) * BST + r] = v.x;
            Bs[(c4 + 1) * BST + r] = v.y;
            Bs[(c4 + 2) * BST + r] = v.z;
            Bs[(c4 + 3) * BST + r] = v.w;
        }
        __syncthreads();

#pragma unroll
        for (int kk = 0; kk < BK; ++kk) {
            float4 a0 = *(const float4*)&As[kk * AST + 8 * ty];
            float4 a1 = *(const float4*)&As[kk * AST + 8 * ty + 4];
            float4 b0 = *(const float4*)&Bs[kk * BST + 4 * tx];
            float a[8] = {a0.x, a0.y, a0.z, a0.w, a1.x, a1.y, a1.z, a1.w};
            float b[4] = {b0.x, b0.y, b0.z, b0.w};
#pragma unroll
            for (int i = 0; i < 8; ++i)
#pragma unroll
                for (int j = 0; j < 4; ++j)
                    acc[i][j] = fmaf(a[i], b[j], acc[i][j]);
        }
        __syncthreads();
    }

    float bb[4];
#pragma unroll
    for (int j = 0; j < 4; ++j) bb[j] = bW[n0 + 4 * tx + j];

#pragma unroll
    for (int i = 0; i < 8; ++i) {
        size_t off = (size_t)(m0 + 8 * ty + i) * H_ + n0 + 4 * tx;
        float4 v = make_float4(acc[i][0] + bb[0], acc[i][1] + bb[1],
                               acc[i][2] + bb[2], acc[i][3] + bb[3]);
        *(float4*)&C[off] = v;
    }
}

// ---------------------------------------------------------------------------
// Kernel B: persistent scan.
// 128 blocks x 256 threads, 1 block/SM (196 KB smem forces it; 128 <= 148 SMs
// so all blocks are co-resident -> software grid barrier is safe).
// Block (bh, cg): batches [bh*32, bh*32+32), cols [cg*16, cg*16+16).
// Warp w owns column pair (2w, 2w+1); lane l owns batch bh*32+l.
// U slice [16][1024] lives in shared the whole kernel (warp-uniform broadcast
// reads). h3 of the previous step staged into shared each step with pad-1025
// rows: both the staging STS (consecutive k per lane) and the compute LDS
// (bank = (l+k) mod 32) are conflict-free.
// ---------------------------------------------------------------------------
#define USH_FLOATS (16 * 1024)
#define HSH_STRIDE 1025
#define HSH_FLOATS (32 * HSH_STRIDE)
#define SCAN_SMEM  ((USH_FLOATS + HSH_FLOATS) * sizeof(float))

__global__ __launch_bounds__(256, 1)
void scan_kernel(float* __restrict__ out, const float* __restrict__ U,
                 const float* __restrict__ bU) {
    extern __shared__ float smem[];
    float* U_sh = smem;                 // [16][1024]
    float* h_sh = smem + USH_FLOATS;    // [32][1025]

    const int tid = threadIdx.x;
    const int l   = tid & 31;
    const int w   = tid >> 5;           // 0..7
    const int bh  = blockIdx.x & 1;
    const int cg  = blockIdx.x >> 1;    // 0..63
    const int b   = bh * 32 + l;
    const int n0  = cg * 16 + 2 * w;
    const int n1  = n0 + 1;

    // Load this block's U slice once (reused for all 512 steps)
    {
        const float* Usrc = U + (size_t)(cg * 16) * H_;
        for (int i = tid; i < USH_FLOATS; i += 256) U_sh[i] = Usrc[i];
    }
    const float bU0 = bU[n0];
    const float bU1 = bU[n1];
    __syncthreads();

    float* o_row = out + (size_t)b * T_ * H_;   // out1[b, :, :]

    // tau = 0: h3 = tanh(xw[:,0,:] + 0)
    {
        float h0 = tanhf(o_row[n0]);
        float h1 = tanhf(o_row[n1]);
        o_row[n0] = h0;
        o_row[n1] = h1;
        g_h[0][b * H_ + n0] = h0;
        g_h[0][b * H_ + n1] = h1;
    }

    const float4* u0p = (const float4*)(U_sh + (size_t)(2 * w) * 1024);
    const float4* u1p = (const float4*)(U_sh + (size_t)(2 * w + 1) * 1024);
    const float*  hp  = h_sh + l * HSH_STRIDE;

    for (int tau = 1; tau < T_; ++tau) {
        grid_barrier();   // all g_h[cur] writes visible

        const int cur = (tau - 1) & 1;
        const int nxt = tau & 1;

        // stage previous h3 (my 32 batch rows) into shared; __ldcg bypasses
        // possibly-stale L1 lines from two steps ago (same buffer).
        {
            const float* src = &g_h[cur][(size_t)(bh * 32) * H_];
#pragma unroll 8
            for (int i = tid; i < 32 * H_; i += 256)
                h_sh[(i >> 10) * HSH_STRIDE + (i & 1023)] = __ldcg(src + i);
        }
        __syncthreads();

        // prefetch xw for this step early (DRAM latency overlaps the k-loop)
        float xw0 = __ldcg(o_row + (size_t)tau * H_ + n0);
        float xw1 = __ldcg(o_row + (size_t)tau * H_ + n1);

        float acc0 = 0.f, acc1 = 0.f;
#pragma unroll 8
        for (int k4 = 0; k4 < 256; ++k4) {
            float4 u0 = u0p[k4];            // warp-uniform broadcast
            float4 u1 = u1p[k4];
            float h0 = hp[4 * k4 + 0];
            float h1 = hp[4 * k4 + 1];
            float h2 = hp[4 * k4 + 2];
            float h3 = hp[4 * k4 + 3];
            acc0 = fmaf(h0, u0.x, acc0);
            acc1 = fmaf(h0, u1.x, acc1);
            acc0 = fmaf(h1, u0.y, acc0);
            acc1 = fmaf(h1, u1.y, acc1);
            acc0 = fmaf(h2, u0.z, acc0);
            acc1 = fmaf(h2, u1.z, acc1);
            acc0 = fmaf(h3, u0.w, acc0);
            acc1 = fmaf(h3, u1.w, acc1);
        }

        float h3_0 = tanhf(xw0 + acc0 + bU0);
        float h3_1 = tanhf(xw1 + acc1 + bU1);

        o_row[(size_t)tau * H_ + n0] = h3_0;
        o_row[(size_t)tau * H_ + n1] = h3_1;
        g_h[nxt][b * H_ + n0] = h3_0;
        g_h[nxt][b * H_ + n1] = h3_1;

        if (tau == T_ - 1) {
            float* out2 = out + (size_t)M_ * H_;
            out2[b * H_ + n0] = h3_0;
            out2[b * H_ + n1] = h3_1;
        }
        // next iteration's grid_barrier() starts with __syncthreads(),
        // which protects h_sh reuse.
    }
}

// ---------------------------------------------------------------------------
// Launch
// ---------------------------------------------------------------------------
extern "C" void kernel_launch(void* const* d_in, const int* in_sizes, int n_in,
                              void* d_out, int out_size) {
    const float* x  = (const float*)d_in[0];   // [B,T,I]
    const float* W  = (const float*)d_in[1];   // [H,I]
    const float* bW = (const float*)d_in[2];   // [H]
    const float* U  = (const float*)d_in[3];   // [H,H]
    const float* bU = (const float*)d_in[4];   // [H]
    float* out = (float*)d_out;                // [B*T*H] out1 ++ [B*H] out2

    // Kernel A: xw -> out1 region (in-place source for the scan)
    dim3 gA(H_ / BN, M_ / BM);   // (16, 256)
    xw_gemm_kernel<<<gA, 256>>>(x, W, bW, out);

    // Kernel B: persistent scan (opt-in large dynamic smem)
    cudaFuncSetAttribute(scan_kernel, cudaFuncAttributeMaxDynamicSharedMemorySize,
                         (int)SCAN_SMEM);
    scan_kernel<<<SCAN_BLOCKS, 256, SCAN_SMEM>>>(out, U, bU);
}